// round 1
// baseline (speedup 1.0000x reference)
#include <cuda_runtime.h>
#include <cstdint>
#include <math.h>

#define T_STEPS 512
#define BATCH   256
#define IN_DIMV 129
#define HID     768
#define OUTD    128
#define KDIM    897           // HID + IN_DIMV
#define NCTA    128
#define UPC     6             // hidden units per CTA (128*6 = 768)
#define GROWS   24            // gate rows per CTA (4 gates * 6 units)
#define WSTR    929           // padded weight stride (odd -> no bank conflicts)
#define KTILE   32
#define NKT     29            // ceil(897/32)
#define DEC_T   256           // decoded timesteps (second half)

// ---------------- static device scratch (no allocations allowed) -------------
__device__ float    g_xT[(size_t)T_STEPS * IN_DIMV * BATCH];   // [t][d][b]
__device__ float    g_hbuf0[HID * BATCH];                      // [k][b]
__device__ float    g_hbuf1[HID * BATCH];
__device__ float    g_hist[(size_t)DEC_T * HID * BATCH];       // [t'][k][b]
__device__ float    g_WdecT[HID * OUTD];                       // [k][o]
__device__ unsigned g_barcnt;
__device__ unsigned g_bargen;

// ---------------- grid barrier (all 128 CTAs resident: 1 CTA/SM) -------------
__device__ __forceinline__ void gridbar() {
    __syncthreads();
    if (threadIdx.x == 0) {
        __threadfence();
        unsigned gen = *(volatile unsigned*)&g_bargen;
        if (atomicAdd(&g_barcnt, 1u) == NCTA - 1u) {
            atomicExch(&g_barcnt, 0u);
            __threadfence();
            atomicAdd(&g_bargen, 1u);
        } else {
            while (*(volatile unsigned*)&g_bargen == gen) { }
        }
        __threadfence();
    }
    __syncthreads();
}

// ---------------- prep kernels ----------------------------------------------
__global__ void zero_h_kernel() {
    int i = blockIdx.x * blockDim.x + threadIdx.x;
    if (i < HID * BATCH) { g_hbuf0[i] = 0.f; g_hbuf1[i] = 0.f; }
}

// seq[t][b][d] -> xT[t][d][b]
__global__ void transpose_x_kernel(const float* __restrict__ seq) {
    __shared__ float tile[32][33];
    int t = blockIdx.z;
    int d0 = blockIdx.x * 32, b0 = blockIdx.y * 32;
    int tx = threadIdx.x, ty = threadIdx.y;
    #pragma unroll
    for (int i = 0; i < 32; i += 8) {
        int d = d0 + tx, b = b0 + ty + i;
        tile[ty + i][tx] = (d < IN_DIMV) ? seq[((size_t)t * BATCH + b) * IN_DIMV + d] : 0.f;
    }
    __syncthreads();
    #pragma unroll
    for (int i = 0; i < 32; i += 8) {
        int d = d0 + ty + i, b = b0 + tx;
        if (d < IN_DIMV)
            g_xT[((size_t)t * IN_DIMV + d) * BATCH + b] = tile[tx][ty + i];
    }
}

// Wdec[o][k] -> WdecT[k][o]
__global__ void transpose_wdec_kernel(const float* __restrict__ Wdec) {
    __shared__ float tile[32][33];
    int k0 = blockIdx.x * 32, o0 = blockIdx.y * 32;
    int tx = threadIdx.x, ty = threadIdx.y;
    #pragma unroll
    for (int i = 0; i < 32; i += 8)
        tile[ty + i][tx] = Wdec[(size_t)(o0 + ty + i) * HID + k0 + tx];
    __syncthreads();
    #pragma unroll
    for (int i = 0; i < 32; i += 8)
        g_WdecT[(size_t)(k0 + ty + i) * OUTD + o0 + tx] = tile[tx][ty + i];
}

// ---------------- persistent fused LSTM kernel -------------------------------
// SMEM: ws[GROWS*WSTR] | hxs[KTILE*BATCH] | gates[GROWS*BATCH] | cs[UPC*BATCH] | bias[32]
#define SMEM_FLOATS (GROWS * WSTR + KTILE * BATCH + GROWS * BATCH + UPC * BATCH + 32)
#define SMEM_MAIN   (SMEM_FLOATS * 4)

__global__ void __launch_bounds__(256, 1)
lstm_kernel(const float* __restrict__ Wih, const float* __restrict__ Whh,
            const float* __restrict__ bih, const float* __restrict__ bhh) {
    extern __shared__ float sm[];
    float* ws    = sm;                                  // 24 x 929
    float* hxs   = ws + GROWS * WSTR;                   // 32 x 256
    float* gates = hxs + KTILE * BATCH;                 // 24 x 256
    float* cs    = gates + GROWS * BATCH;               // 6 x 256
    float* bias  = cs + UPC * BATCH;                    // 24 (+pad)

    const int tid = threadIdx.x;
    const int cta = blockIdx.x;

    // stage fused weights: row r -> gate type r/6, unit (cta*6 + r%6)
    for (int e = tid; e < GROWS * WSTR; e += 256) {
        int r = e / WSTR, k = e - r * WSTR;
        int gr = (r / UPC) * HID + cta * UPC + (r % UPC);
        float v = 0.f;
        if (k < HID)       v = Whh[(size_t)gr * HID + k];
        else if (k < KDIM) v = Wih[(size_t)gr * IN_DIMV + (k - HID)];
        ws[e] = v;
    }
    if (tid < GROWS) {
        int r = tid;
        int gr = (r / UPC) * HID + cta * UPC + (r % UPC);
        bias[r] = bih[gr] + bhh[gr];
    }
    for (int e = tid; e < UPC * BATCH; e += 256) cs[e] = 0.f;
    __syncthreads();

    const int gid = tid & 7;        // gate-row group (3 rows)
    const int bid = tid >> 3;       // batch group (8 cols)
    const int bb  = bid * 8;
    const int r0  = gid * 3;

    float a[3][8];

    for (int t = 0; t < T_STEPS; t++) {
        const float* hread  = (t & 1) ? g_hbuf1 : g_hbuf0;
        float*       hwrite = (t & 1) ? g_hbuf0 : g_hbuf1;

        #pragma unroll
        for (int q = 0; q < 3; q++) {
            float bv = bias[r0 + q];
            #pragma unroll
            for (int x = 0; x < 8; x++) a[q][x] = bv;
        }

        for (int kt = 0; kt < NKT; kt++) {
            const int k0 = kt * KTILE;
            // stage hx tile [KTILE][BATCH] : h rows then x rows (zero pad past 897)
            #pragma unroll
            for (int i = 0; i < 8; i++) {
                int f4  = i * 256 + tid;
                int row = f4 >> 6;
                int col = (f4 & 63) << 2;
                int k   = k0 + row;
                float4 v = make_float4(0.f, 0.f, 0.f, 0.f);
                if (k < HID)
                    v = *(const float4*)&hread[k * BATCH + col];
                else if (k < KDIM)
                    v = *(const float4*)&g_xT[((size_t)t * IN_DIMV + (k - HID)) * BATCH + col];
                *(float4*)&hxs[row * BATCH + col] = v;
            }
            __syncthreads();

            #pragma unroll 8
            for (int kk = 0; kk < KTILE; kk++) {
                const float4 h0 = *(const float4*)&hxs[kk * BATCH + bb];
                const float4 h1 = *(const float4*)&hxs[kk * BATCH + bb + 4];
                float hv[8] = {h0.x, h0.y, h0.z, h0.w, h1.x, h1.y, h1.z, h1.w};
                #pragma unroll
                for (int q = 0; q < 3; q++) {
                    float w = ws[(r0 + q) * WSTR + k0 + kk];
                    #pragma unroll
                    for (int x = 0; x < 8; x++) a[q][x] += w * hv[x];
                }
            }
            __syncthreads();
        }

        // exchange gate pre-activations through SMEM
        #pragma unroll
        for (int q = 0; q < 3; q++) {
            *(float4*)&gates[(r0 + q) * BATCH + bb]     = make_float4(a[q][0], a[q][1], a[q][2], a[q][3]);
            *(float4*)&gates[(r0 + q) * BATCH + bb + 4] = make_float4(a[q][4], a[q][5], a[q][6], a[q][7]);
        }
        __syncthreads();

        // elementwise update: thread tid handles batch=tid for all 6 owned units
        #pragma unroll
        for (int u = 0; u < UPC; u++) {
            float xi = gates[(u)      * BATCH + tid];
            float xf = gates[(6 + u)  * BATCH + tid];
            float xg = gates[(12 + u) * BATCH + tid];
            float xo = gates[(18 + u) * BATCH + tid];
            float ig = 1.f / (1.f + expf(-xi));
            float fg = 1.f / (1.f + expf(-xf));
            float gg = tanhf(xg);
            float og = 1.f / (1.f + expf(-xo));
            float c  = fg * cs[u * BATCH + tid] + ig * gg;
            cs[u * BATCH + tid] = c;
            float h  = og * tanhf(c);
            int gu = cta * UPC + u;
            hwrite[gu * BATCH + tid] = h;
            if (t >= DEC_T)
                g_hist[(size_t)(t - DEC_T) * (HID * BATCH) + gu * BATCH + tid] = h;
        }
        gridbar();
    }
}

// ---------------- decoder GEMM: out[t][b][o] = hist[t][:,b] . WdecT[:, o] ----
__global__ void __launch_bounds__(256)
decode_kernel(const float* __restrict__ bdec, float* __restrict__ out) {
    __shared__ float wt[KTILE * 32];
    const int og  = blockIdx.x;     // 4 groups of 32 output cols
    const int t   = blockIdx.y;     // 256 timesteps
    const int tid = threadIdx.x;    // batch index

    float acc[32];
    #pragma unroll
    for (int i = 0; i < 32; i++) acc[i] = 0.f;

    for (int kt = 0; kt < HID / KTILE; kt++) {
        const int k0 = kt * KTILE;
        #pragma unroll
        for (int i = 0; i < 4; i++) {
            int e = i * 256 + tid;
            int kk = e >> 5, oo = e & 31;
            wt[e] = g_WdecT[(size_t)(k0 + kk) * OUTD + og * 32 + oo];
        }
        __syncthreads();
        #pragma unroll 8
        for (int kk = 0; kk < KTILE; kk++) {
            float hv = g_hist[((size_t)t * HID + k0 + kk) * BATCH + tid];
            #pragma unroll
            for (int o4 = 0; o4 < 8; o4++) {
                float4 w = *(const float4*)&wt[kk * 32 + o4 * 4];
                acc[o4 * 4 + 0] += hv * w.x;
                acc[o4 * 4 + 1] += hv * w.y;
                acc[o4 * 4 + 2] += hv * w.z;
                acc[o4 * 4 + 3] += hv * w.w;
            }
        }
        __syncthreads();
    }

    size_t ob = ((size_t)t * BATCH + tid) * OUTD + og * 32;
    #pragma unroll
    for (int o4 = 0; o4 < 8; o4++) {
        float4 r;
        r.x = acc[o4 * 4 + 0] + bdec[og * 32 + o4 * 4 + 0];
        r.y = acc[o4 * 4 + 1] + bdec[og * 32 + o4 * 4 + 1];
        r.z = acc[o4 * 4 + 2] + bdec[og * 32 + o4 * 4 + 2];
        r.w = acc[o4 * 4 + 3] + bdec[og * 32 + o4 * 4 + 3];
        *(float4*)&out[ob + o4 * 4] = r;
    }
}

// ---------------- launch -----------------------------------------------------
extern "C" void kernel_launch(void* const* d_in, const int* in_sizes, int n_in,
                              void* d_out, int out_size) {
    const float* seq  = (const float*)d_in[0];
    const float* Wih  = (const float*)d_in[1];
    const float* Whh  = (const float*)d_in[2];
    const float* bih  = (const float*)d_in[3];
    const float* bhh  = (const float*)d_in[4];
    const float* Wdec = (const float*)d_in[5];
    const float* bdec = (const float*)d_in[6];
    float* out = (float*)d_out;

    cudaFuncSetAttribute(lstm_kernel, cudaFuncAttributeMaxDynamicSharedMemorySize, SMEM_MAIN);

    zero_h_kernel<<<(HID * BATCH + 255) / 256, 256>>>();
    dim3 tb(32, 8);
    transpose_x_kernel<<<dim3(5, 8, T_STEPS), tb>>>(seq);
    transpose_wdec_kernel<<<dim3(HID / 32, OUTD / 32), tb>>>(Wdec);
    lstm_kernel<<<NCTA, 256, SMEM_MAIN>>>(Wih, Whh, bih, bhh);
    decode_kernel<<<dim3(4, DEC_T), 256>>>(bdec, out);
}